// round 1
// baseline (speedup 1.0000x reference)
#include <cuda_runtime.h>
#include <math.h>

#define NN 1024
#define KK 32
#define HH 256
#define DEn 128
#define NE 8
#define NHn 8
#define DHn 32
#define FF 512
#define SS 257   // padded slot stride (bank-conflict-free head slicing)

__device__ int   g_te[NN * 2];
__device__ float g_tg[NN * 2];

__device__ __forceinline__ float gelu_f(float x) {
    float x3 = x * x * x;
    return 0.5f * x * (1.0f + tanhf(0.7978845608028654f * (x + 0.044715f * x3)));
}

__device__ __forceinline__ float block_sum256(float v, float* red) {
    #pragma unroll
    for (int o = 16; o; o >>= 1) v += __shfl_xor_sync(0xffffffffu, v, o);
    int tid = threadIdx.x;
    if ((tid & 31) == 0) red[tid >> 5] = v;
    __syncthreads();
    float s = red[0] + red[1] + red[2] + red[3] + red[4] + red[5] + red[6] + red[7];
    __syncthreads();
    return s;
}

// ---- 16-row x 2-col register-blocked GEMM helpers (256 threads cover 32x256) ----
__device__ __forceinline__ void init16x2(float acc[16][2], const float* bias, int cg) {
    float b0 = bias[cg], b1 = bias[cg + 128];
    #pragma unroll
    for (int r = 0; r < 16; r++) { acc[r][0] = b0; acc[r][1] = b1; }
}

__device__ __forceinline__ void gemm_acc16x2(float acc[16][2],
    const float* __restrict__ sIn, int inStride, int hin,
    const float* __restrict__ W, int wld, int cg, int rg)
{
    const float* inp = sIn + rg * 16 * inStride;
    #pragma unroll 2
    for (int i = 0; i < hin; i++) {
        float w0 = W[(size_t)i * wld + cg];
        float w1 = W[(size_t)i * wld + cg + 128];
        #pragma unroll
        for (int r = 0; r < 16; r++) {
            float x = inp[r * inStride + i];
            acc[r][0] = fmaf(x, w0, acc[r][0]);
            acc[r][1] = fmaf(x, w1, acc[r][1]);
        }
    }
}

__device__ __forceinline__ void store16x2(const float acc[16][2], float* sOut,
                                          int outStride, int cg, int rg, bool doGelu) {
    #pragma unroll
    for (int r = 0; r < 16; r++) {
        float v0 = acc[r][0], v1 = acc[r][1];
        if (doGelu) { v0 = gelu_f(v0); v1 = gelu_f(v1); }
        sOut[(rg * 16 + r) * outStride + cg] = v0;
        sOut[(rg * 16 + r) * outStride + cg + 128] = v1;
    }
}

// ---------------- gating kernel: top-2 experts per node ----------------
__global__ void gate_kernel(const float* __restrict__ nf, const float* __restrict__ wg) {
    int n = blockIdx.x;
    int tid = threadIdx.x;   // 256 threads, one per H element
    float x = nf[n * HH + tid];
    float p[NE];
    #pragma unroll
    for (int e = 0; e < NE; e++) p[e] = x * wg[tid * NE + e];
    #pragma unroll
    for (int e = 0; e < NE; e++)
        #pragma unroll
        for (int o = 16; o; o >>= 1) p[e] += __shfl_xor_sync(0xffffffffu, p[e], o);
    __shared__ float logits[NE];
    if (tid < NE) logits[tid] = 0.f;
    __syncthreads();
    if ((tid & 31) == 0) {
        #pragma unroll
        for (int e = 0; e < NE; e++) atomicAdd(&logits[e], p[e]);
    }
    __syncthreads();
    if (tid == 0) {
        float v0 = -1e30f, v1 = -1e30f; int i0 = 0, i1 = 0;
        for (int e = 0; e < NE; e++) {
            float v = logits[e];
            if (v > v0) { v1 = v0; i1 = i0; v0 = v; i0 = e; }
            else if (v > v1) { v1 = v; i1 = e; }
        }
        float e1 = expf(v1 - v0);
        float g0 = 1.f / (1.f + e1);
        g_te[n * 2 + 0] = i0; g_te[n * 2 + 1] = i1;
        g_tg[n * 2 + 0] = g0; g_tg[n * 2 + 1] = 1.f - g0;
    }
}

// ---------------- main kernel: one CTA per node ----------------
__global__ __launch_bounds__(256) void moe_kernel(
    const float* __restrict__ node_features,
    const float* __restrict__ edge_features,
    const float* __restrict__ edge_raw,
    const int*   __restrict__ neighbor_list,
    const float* __restrict__ neighbor_mask,
    const float* __restrict__ attn_mask,
    const float* __restrict__ W_edge, const float* __restrict__ b_edge,
    const float* __restrict__ W_node, const float* __restrict__ b_node,
    const float* __restrict__ W_msg,  const float* __restrict__ b_msg,
    const float* __restrict__ W_qkv,  const float* __restrict__ b_qkv,
    const float* __restrict__ W_out,  const float* __restrict__ b_out,
    const float* __restrict__ lag_, const float* __restrict__ lab_,
    const float* __restrict__ lfg_, const float* __restrict__ lfb_,
    const float* __restrict__ W1n, const float* __restrict__ b1n,
    const float* __restrict__ W2n, const float* __restrict__ b2n,
    const float* __restrict__ W1e, const float* __restrict__ b1e,
    const float* __restrict__ W2e, const float* __restrict__ b2e,
    float* __restrict__ out)
{
    extern __shared__ float sm[];
    float* sA   = sm;                 // KK*SS
    float* sB   = sA + KK * SS;
    float* sC   = sB + KK * SS;
    float* sD   = sC + KK * SS;
    float* sHid = sD + KK * SS;       // KK*FF
    float* sNh  = sHid + KK * FF;     // HH
    float* sVec = sNh + HH;           // HH
    float* sHn  = sVec + HH;          // FF
    float* sMsk = sHn + FF;           // KK
    float* sRed = sMsk + KK;          // 8

    const int n = blockIdx.x;
    const int tid = threadIdx.x;
    const int lane = tid & 31, wid = tid >> 5;
    const int j = tid;                 // column for thread-per-column stages
    const int cg = tid & 127;          // col group for 16x2 gemm
    const int rg = tid >> 7;           // row group (0/1)

    if (tid < KK) sMsk[tid] = neighbor_mask[n * KK + tid];
    __syncthreads();
    float cnt = 0.f;
    #pragma unroll
    for (int k = 0; k < KK; k++) cnt += sMsk[k];
    float inv_cnt = 1.f / (cnt + 1e-5f);

    const float xj = node_features[(size_t)n * HH + j];

    #pragma unroll 1
    for (int slot = 0; slot < 2; slot++) {
        int e = g_te[n * 2 + slot];
        float gate = g_tg[n * 2 + slot];
        const float* lag = lag_ + e * HH;
        const float* lab = lab_ + e * HH;
        const float* lfg = lfg_ + e * HH;
        const float* lfb = lfb_ + e * HH;

        // ---- recv layernorm (block-wide, thread = element) -> sNh ----
        {
            float s = block_sum256(xj, sRed);
            float mu = s * (1.f / HH);
            float d = xj - mu;
            float q = block_sum256(d * d, sRed);
            float rs = rsqrtf(q * (1.f / HH) + 1e-5f);
            sNh[j] = d * rs * lag[j] + lab[j];
        }
        __syncthreads();

        // ---- rv[j] = recv @ Wn_bottom + bn  -> sVec ----
        {
            const float* W = W_node + (size_t)e * 2 * HH * HH + (size_t)HH * HH;
            float acc = b_node[e * HH + j];
            #pragma unroll 4
            for (int i = 0; i < HH; i++) acc = fmaf(sNh[i], W[i * HH + j], acc);
            sVec[j] = acc;
        }

        // ---- load edge_raw tile -> sB [KK][DEn] ----
        for (int idx = tid; idx < KK * DEn; idx += 256)
            sB[idx] = edge_raw[(size_t)n * KK * DEn + idx];
        __syncthreads();

        // ---- eh = gelu(edge_raw @ We + be) -> sA ----
        {
            float acc[16][2];
            init16x2(acc, b_edge + e * HH, cg);
            gemm_acc16x2(acc, sB, DEn, DEn, W_edge + (size_t)e * DEn * HH, HH, cg, rg);
            store16x2(acc, sA, SS, cg, rg, true);
        }
        __syncthreads();

        // ---- sender = LN(node_features[nbr]) -> sB (warp per row) ----
        for (int k = wid; k < KK; k += 8) {
            int nbr = neighbor_list[n * KK + k];
            const float* x = node_features + (size_t)nbr * HH;
            float v[8]; float s = 0.f;
            #pragma unroll
            for (int i = 0; i < 8; i++) { v[i] = x[lane + 32 * i]; s += v[i]; }
            #pragma unroll
            for (int o = 16; o; o >>= 1) s += __shfl_xor_sync(0xffffffffu, s, o);
            float mu = s * (1.f / HH);
            float q = 0.f;
            #pragma unroll
            for (int i = 0; i < 8; i++) { float d = v[i] - mu; q += d * d; }
            #pragma unroll
            for (int o = 16; o; o >>= 1) q += __shfl_xor_sync(0xffffffffu, q, o);
            float rs = rsqrtf(q * (1.f / HH) + 1e-5f);
            #pragma unroll
            for (int i = 0; i < 8; i++) {
                int c = lane + 32 * i;
                sB[k * SS + c] = (v[i] - mu) * rs * lag[c] + lab[c];
            }
        }
        __syncthreads();

        // ---- nodeh = gelu(sender@Wn_top + rv) -> sC ----
        {
            float acc[16][2];
            init16x2(acc, sVec, cg);
            gemm_acc16x2(acc, sB, SS, HH, W_node + (size_t)e * 2 * HH * HH, HH, cg, rg);
            store16x2(acc, sC, SS, cg, rg, true);
        }
        __syncthreads();

        // ---- msg = gelu(eh@Wm_top + nodeh@Wm_bot + bm) -> sB ----
        {
            const float* Wt = W_msg + (size_t)e * 2 * HH * HH;
            float acc[16][2];
            init16x2(acc, b_msg + e * HH, cg);
            gemm_acc16x2(acc, sA, SS, HH, Wt, HH, cg, rg);
            gemm_acc16x2(acc, sC, SS, HH, Wt + (size_t)HH * HH, HH, cg, rg);
            store16x2(acc, sB, SS, cg, rg, true);
        }
        __syncthreads();

        // ---- qkv = msg @ Wqkv + bqkv : q->sA, k->sC, v->sD ----
        {
            const float* W = W_qkv + (size_t)e * HH * 3 * HH;
            const float* bq = b_qkv + e * 3 * HH;
            float* dst0[3] = { sA, sC, sD };
            #pragma unroll 1
            for (int p = 0; p < 3; p++) {
                float acc[16][2];
                init16x2(acc, bq + p * HH, cg);
                gemm_acc16x2(acc, sB, SS, HH, W + p * HH, 3 * HH, cg, rg);
                store16x2(acc, dst0[p], SS, cg, rg, false);
            }
        }
        __syncthreads();

        // ---- attention: warp = head, lane = query row. out -> sB ----
        {
            int h = wid;
            int a = lane;
            float qv[DHn];
            #pragma unroll
            for (int d = 0; d < DHn; d++) qv[d] = sA[a * SS + h * DHn + d];
            float sc[KK];
            const float scale = 0.17677669529663687f;   // 1/sqrt(32)
            #pragma unroll
            for (int b = 0; b < KK; b++) {
                float s = 0.f;
                #pragma unroll
                for (int d = 0; d < DHn; d++) s = fmaf(qv[d], sC[b * SS + h * DHn + d], s);
                sc[b] = s * scale + attn_mask[n * KK + b];
            }
            float m = sc[0];
            #pragma unroll
            for (int b = 1; b < KK; b++) m = fmaxf(m, sc[b]);
            float ssum = 0.f;
            #pragma unroll
            for (int b = 0; b < KK; b++) { sc[b] = expf(sc[b] - m); ssum += sc[b]; }
            float inv = 1.f / ssum;
            float o[DHn];
            #pragma unroll
            for (int d = 0; d < DHn; d++) o[d] = 0.f;
            #pragma unroll
            for (int b = 0; b < KK; b++) {
                float p = sc[b] * inv;
                #pragma unroll
                for (int d = 0; d < DHn; d++) o[d] = fmaf(p, sD[b * SS + h * DHn + d], o[d]);
            }
            #pragma unroll
            for (int d = 0; d < DHn; d++) sB[a * SS + h * DHn + d] = o[d];
        }
        __syncthreads();

        // ---- edge_out = attn_out @ Wo + bo -> sD ----
        {
            float acc[16][2];
            init16x2(acc, b_out + e * HH, cg);
            gemm_acc16x2(acc, sB, SS, HH, W_out + (size_t)e * HH * HH, HH, cg, rg);
            store16x2(acc, sD, SS, cg, rg, false);
        }
        __syncthreads();

        // ---- masked-mean aggregate -> nf ; then ef = edge_out + edge_features ----
        float nfj;
        {
            float s = 0.f;
            #pragma unroll
            for (int k = 0; k < KK; k++) s += sD[k * SS + j] * sMsk[k];
            nfj = s * inv_cnt + xj;
            #pragma unroll
            for (int k = 0; k < KK; k++)
                sD[k * SS + j] += edge_features[((size_t)n * KK + k) * HH + j];
        }
        __syncthreads();

        // ---- node FFN ----
        float node_final;
        {
            float s = block_sum256(nfj, sRed);
            float mu = s * (1.f / HH);
            float d = nfj - mu;
            float q = block_sum256(d * d, sRed);
            float rs = rsqrtf(q * (1.f / HH) + 1e-5f);
            sVec[j] = d * rs * lfg[j] + lfb[j];
        }
        __syncthreads();
        {
            const float* W = W1n + (size_t)e * HH * FF;
            const float* bb = b1n + e * FF;
            float a0 = bb[j], a1 = bb[j + 256];
            #pragma unroll 4
            for (int i = 0; i < HH; i++) {
                float x = sVec[i];
                a0 = fmaf(x, W[(size_t)i * FF + j], a0);
                a1 = fmaf(x, W[(size_t)i * FF + j + 256], a1);
            }
            sHn[j] = gelu_f(a0);
            sHn[j + 256] = gelu_f(a1);
        }
        __syncthreads();
        {
            const float* W = W2n + (size_t)e * FF * HH;
            float acc = b2n[e * HH + j];
            #pragma unroll 4
            for (int mth = 0; mth < FF; mth++) acc = fmaf(sHn[mth], W[(size_t)mth * HH + j], acc);
            node_final = nfj + acc;
        }

        // ---- edge FFN: eh2 = LN(ef) -> sA ----
        for (int k = wid; k < KK; k += 8) {
            float v[8]; float s = 0.f;
            #pragma unroll
            for (int i = 0; i < 8; i++) { v[i] = sD[k * SS + lane + 32 * i]; s += v[i]; }
            #pragma unroll
            for (int o = 16; o; o >>= 1) s += __shfl_xor_sync(0xffffffffu, s, o);
            float mu = s * (1.f / HH);
            float q = 0.f;
            #pragma unroll
            for (int i = 0; i < 8; i++) { float d = v[i] - mu; q += d * d; }
            #pragma unroll
            for (int o = 16; o; o >>= 1) q += __shfl_xor_sync(0xffffffffu, q, o);
            float rs = rsqrtf(q * (1.f / HH) + 1e-5f);
            #pragma unroll
            for (int i = 0; i < 8; i++) {
                int c = lane + 32 * i;
                sA[k * SS + c] = (v[i] - mu) * rs * lfg[c] + lfb[c];
            }
        }
        __syncthreads();

        // ---- hidden_e = gelu(eh2 @ W1e + b1e) -> sHid [KK x FF] ----
        {
            const float* W = W1e + (size_t)e * HH * FF;
            const float* bb = b1e + e * FF;
            #pragma unroll 1
            for (int p = 0; p < 2; p++) {
                float acc[16][2];
                init16x2(acc, bb + p * 256, cg);
                gemm_acc16x2(acc, sA, SS, HH, W + p * 256, FF, cg, rg);
                store16x2(acc, sHid + p * 256, FF, cg, rg, true);
            }
        }
        __syncthreads();

        // ---- ef_final = ef + hidden_e @ W2e + b2e ; write edge output ----
        {
            float acc[16][2];
            init16x2(acc, b2e + e * HH, cg);
            gemm_acc16x2(acc, sHid, FF, FF, W2e + (size_t)e * FF * HH, HH, cg, rg);
            float* eout = out + (size_t)NN * HH + (size_t)n * KK * HH;
            if (slot == 0) {
                #pragma unroll
                for (int r = 0; r < 16; r++) {
                    int row = rg * 16 + r;
                    eout[(size_t)row * HH + cg]       = gate * (sD[row * SS + cg] + acc[r][0]);
                    eout[(size_t)row * HH + cg + 128] = gate * (sD[row * SS + cg + 128] + acc[r][1]);
                }
            } else {
                #pragma unroll
                for (int r = 0; r < 16; r++) {
                    int row = rg * 16 + r;
                    eout[(size_t)row * HH + cg]       += gate * (sD[row * SS + cg] + acc[r][0]);
                    eout[(size_t)row * HH + cg + 128] += gate * (sD[row * SS + cg + 128] + acc[r][1]);
                }
            }
        }
        // ---- node output ----
        {
            float* nout = out + (size_t)n * HH;
            if (slot == 0) nout[j] = gate * node_final;
            else           nout[j] += gate * node_final;
        }
        __syncthreads();   // buffers reused by next expert
    }
}

static constexpr int SMEM_FLOATS = 4 * KK * SS + KK * FF + HH + HH + FF + KK + 8;
static constexpr int SMEM_BYTES  = SMEM_FLOATS * 4;

extern "C" void kernel_launch(void* const* d_in, const int* in_sizes, int n_in,
                              void* d_out, int out_size) {
    const float* node_features = (const float*)d_in[0];
    const float* edge_features = (const float*)d_in[1];
    const float* edge_raw      = (const float*)d_in[2];
    const int*   neighbor_list = (const int*)  d_in[3];
    const float* neighbor_mask = (const float*)d_in[4];
    const float* attn_mask     = (const float*)d_in[5];
    const float* w_gate        = (const float*)d_in[6];
    const float* W_edge = (const float*)d_in[7];
    const float* b_edge = (const float*)d_in[8];
    const float* W_node = (const float*)d_in[9];
    const float* b_node = (const float*)d_in[10];
    const float* W_msg  = (const float*)d_in[11];
    const float* b_msg  = (const float*)d_in[12];
    const float* W_qkv  = (const float*)d_in[13];
    const float* b_qkv  = (const float*)d_in[14];
    const float* W_out  = (const float*)d_in[15];
    const float* b_out  = (const float*)d_in[16];
    const float* lag    = (const float*)d_in[17];
    const float* lab    = (const float*)d_in[18];
    const float* lfg    = (const float*)d_in[19];
    const float* lfb    = (const float*)d_in[20];
    const float* W1n = (const float*)d_in[21];
    const float* b1n = (const float*)d_in[22];
    const float* W2n = (const float*)d_in[23];
    const float* b2n = (const float*)d_in[24];
    const float* W1e = (const float*)d_in[25];
    const float* b1e = (const float*)d_in[26];
    const float* W2e = (const float*)d_in[27];
    const float* b2e = (const float*)d_in[28];
    float* out = (float*)d_out;

    cudaFuncSetAttribute(moe_kernel, cudaFuncAttributeMaxDynamicSharedMemorySize, SMEM_BYTES);

    gate_kernel<<<NN, 256>>>(node_features, w_gate);
    moe_kernel<<<NN, 256, SMEM_BYTES>>>(
        node_features, edge_features, edge_raw, neighbor_list, neighbor_mask,
        attn_mask, W_edge, b_edge, W_node, b_node, W_msg, b_msg, W_qkv, b_qkv,
        W_out, b_out, lag, lab, lfg, lfb, W1n, b1n, W2n, b2n, W1e, b1e, W2e, b2e,
        out);
}

// round 2
// speedup vs baseline: 1.4348x; 1.4348x over previous
#include <cuda_runtime.h>
#include <math.h>

#define NN 1024
#define KK 32
#define HH 256
#define DEn 128
#define NE 8
#define NHn 8
#define DHn 32
#define FF 512
#define SS 258   // 8B-aligned padded slot stride

typedef unsigned long long ull;

__device__ int   g_te[NN * 2];
__device__ float g_tg[NN * 2];

__device__ __forceinline__ float gelu_f(float x) {
    float x3 = x * x * x;
    return 0.5f * x * (1.0f + tanhf(0.7978845608028654f * (x + 0.044715f * x3)));
}

__device__ __forceinline__ ull pk2(float lo, float hi) {
    ull r; asm("mov.b64 %0,{%1,%2};" : "=l"(r) : "f"(lo), "f"(hi)); return r;
}
__device__ __forceinline__ void upk2(ull v, float& lo, float& hi) {
    asm("mov.b64 {%0,%1},%2;" : "=f"(lo), "=f"(hi) : "l"(v));
}
__device__ __forceinline__ void fma2(ull& d, ull a, ull b) {
    asm("fma.rn.f32x2 %0,%1,%2,%0;" : "+l"(d) : "l"(a), "l"(b));
}
__device__ __forceinline__ float fold(ull v) {
    float lo, hi; upk2(v, lo, hi); return lo + hi;
}

__device__ __forceinline__ float block_sum512(float v, float* red) {
    #pragma unroll
    for (int o = 16; o; o >>= 1) v += __shfl_xor_sync(0xffffffffu, v, o);
    int tid = threadIdx.x;
    if ((tid & 31) == 0) red[tid >> 5] = v;
    __syncthreads();
    float s = 0.f;
    #pragma unroll
    for (int i = 0; i < 16; i++) s += red[i];
    __syncthreads();
    return s;
}

// ---- 8-row x 2-col f32x2 GEMM: 512 threads cover 32 rows x 256 cols ----
__device__ __forceinline__ void initacc(ull acc[8][2], const float* bias, int c) {
    ull a0 = pk2(bias[c], 0.f), a1 = pk2(bias[c + 128], 0.f);
    #pragma unroll
    for (int r = 0; r < 8; r++) { acc[r][0] = a0; acc[r][1] = a1; }
}

__device__ __forceinline__ void gemm8x2(ull acc[8][2],
    const float* __restrict__ sIn, int inS, int hin,
    const float* __restrict__ W, int wld, int c, int rbase)
{
    const float* ip = sIn + rbase * inS;
    #pragma unroll 2
    for (int k = 0; k < hin; k += 2) {
        const float* wr0 = W + (size_t)k * wld;
        const float* wr1 = wr0 + wld;
        ull wA = pk2(wr0[c], wr1[c]);
        ull wB = pk2(wr0[c + 128], wr1[c + 128]);
        #pragma unroll
        for (int r = 0; r < 8; r++) {
            ull xv = *(const ull*)(ip + r * inS + k);
            fma2(acc[r][0], xv, wA);
            fma2(acc[r][1], xv, wB);
        }
    }
}

__device__ __forceinline__ void storeacc(const ull acc[8][2], float* sOut,
                                         int outS, int c, int rbase, bool doGelu) {
    #pragma unroll
    for (int r = 0; r < 8; r++) {
        float v0 = fold(acc[r][0]), v1 = fold(acc[r][1]);
        if (doGelu) { v0 = gelu_f(v0); v1 = gelu_f(v1); }
        sOut[(rbase + r) * outS + c] = v0;
        sOut[(rbase + r) * outS + c + 128] = v1;
    }
}

// ---------------- gating kernel ----------------
__global__ void gate_kernel(const float* __restrict__ nf, const float* __restrict__ wg) {
    int n = blockIdx.x;
    int tid = threadIdx.x;
    float x = nf[n * HH + tid];
    float p[NE];
    #pragma unroll
    for (int e = 0; e < NE; e++) p[e] = x * wg[tid * NE + e];
    #pragma unroll
    for (int e = 0; e < NE; e++)
        #pragma unroll
        for (int o = 16; o; o >>= 1) p[e] += __shfl_xor_sync(0xffffffffu, p[e], o);
    __shared__ float logits[NE];
    if (tid < NE) logits[tid] = 0.f;
    __syncthreads();
    if ((tid & 31) == 0) {
        #pragma unroll
        for (int e = 0; e < NE; e++) atomicAdd(&logits[e], p[e]);
    }
    __syncthreads();
    if (tid == 0) {
        float v0 = -1e30f, v1 = -1e30f; int i0 = 0, i1 = 0;
        for (int e = 0; e < NE; e++) {
            float v = logits[e];
            if (v > v0) { v1 = v0; i1 = i0; v0 = v; i0 = e; }
            else if (v > v1) { v1 = v; i1 = e; }
        }
        float e1 = expf(v1 - v0);
        float g0 = 1.f / (1.f + e1);
        g_te[n * 2 + 0] = i0; g_te[n * 2 + 1] = i1;
        g_tg[n * 2 + 0] = g0; g_tg[n * 2 + 1] = 1.f - g0;
    }
}

// ---------------- main kernel: one CTA (512 thr) per node ----------------
__global__ __launch_bounds__(512) void moe_kernel(
    const float* __restrict__ node_features,
    const float* __restrict__ edge_features,
    const float* __restrict__ edge_raw,
    const int*   __restrict__ neighbor_list,
    const float* __restrict__ neighbor_mask,
    const float* __restrict__ attn_mask,
    const float* __restrict__ W_edge, const float* __restrict__ b_edge,
    const float* __restrict__ W_node, const float* __restrict__ b_node,
    const float* __restrict__ W_msg,  const float* __restrict__ b_msg,
    const float* __restrict__ W_qkv,  const float* __restrict__ b_qkv,
    const float* __restrict__ W_out,  const float* __restrict__ b_out,
    const float* __restrict__ lag_, const float* __restrict__ lab_,
    const float* __restrict__ lfg_, const float* __restrict__ lfb_,
    const float* __restrict__ W1n, const float* __restrict__ b1n,
    const float* __restrict__ W2n, const float* __restrict__ b2n,
    const float* __restrict__ W1e, const float* __restrict__ b1e,
    const float* __restrict__ W2e, const float* __restrict__ b2e,
    float* __restrict__ out)
{
    extern __shared__ float sm[];
    float* sA   = sm;                 // KK*SS
    float* sB   = sA + KK * SS;
    float* sC   = sB + KK * SS;
    float* sD   = sC + KK * SS;
    float* sHid = sD + KK * SS;       // KK*FF
    float* sNh  = sHid + KK * FF;     // HH
    float* sVec = sNh + HH;           // HH
    float* sHn  = sVec + HH;          // FF
    float* sMsk = sHn + FF;           // KK
    float* sAm  = sMsk + KK;          // KK
    float* sRed = sAm + KK;           // 16

    const int n = blockIdx.x;
    const int tid = threadIdx.x;
    const int lane = tid & 31, wid = tid >> 5;
    const int j = tid;                 // element index for <256 stages
    const int c = tid & 127;           // gemm column
    const int rbase = (tid >> 7) * 8;  // gemm rows

    if (tid < KK) {
        sMsk[tid] = neighbor_mask[n * KK + tid];
        sAm[tid]  = attn_mask[n * KK + tid];
    }
    __syncthreads();
    float cnt = 0.f;
    #pragma unroll
    for (int k = 0; k < KK; k++) cnt += sMsk[k];
    float inv_cnt = 1.f / (cnt + 1e-5f);

    const float xj = (tid < HH) ? node_features[(size_t)n * HH + j] : 0.f;

    #pragma unroll 1
    for (int slot = 0; slot < 2; slot++) {
        int e = g_te[n * 2 + slot];
        float gate = g_tg[n * 2 + slot];
        const float* lag = lag_ + e * HH;
        const float* lab = lab_ + e * HH;
        const float* lfg = lfg_ + e * HH;
        const float* lfb = lfb_ + e * HH;

        // ---- recv layernorm -> sNh ----
        {
            float s = block_sum512(xj, sRed);
            float mu = s * (1.f / HH);
            float d = (tid < HH) ? (xj - mu) : 0.f;
            float q = block_sum512(d * d, sRed);
            float rs = rsqrtf(q * (1.f / HH) + 1e-5f);
            if (tid < HH) sNh[j] = d * rs * lag[j] + lab[j];
        }
        __syncthreads();

        // ---- rv = recv @ Wn_bottom + bn -> sVec ----
        if (tid < HH) {
            const float* W = W_node + (size_t)e * 2 * HH * HH + (size_t)HH * HH;
            float acc = b_node[e * HH + j];
            #pragma unroll 4
            for (int i = 0; i < HH; i++) acc = fmaf(sNh[i], W[i * HH + j], acc);
            sVec[j] = acc;
        }

        // ---- load edge_raw tile (dense stride DEn) -> sB ----
        for (int idx = tid; idx < KK * DEn; idx += 512)
            sB[idx] = edge_raw[(size_t)n * KK * DEn + idx];
        __syncthreads();

        // ---- eh = gelu(edge_raw @ We + be) -> sA ----
        {
            ull acc[8][2];
            initacc(acc, b_edge + e * HH, c);
            gemm8x2(acc, sB, DEn, DEn, W_edge + (size_t)e * DEn * HH, HH, c, rbase);
            storeacc(acc, sA, SS, c, rbase, true);
        }
        __syncthreads();

        // ---- sender = LN(node_features[nbr]) -> sB (warp per row) ----
        for (int k = wid; k < KK; k += 16) {
            int nbr = neighbor_list[n * KK + k];
            const float* x = node_features + (size_t)nbr * HH;
            float v[8]; float s = 0.f;
            #pragma unroll
            for (int i = 0; i < 8; i++) { v[i] = x[lane + 32 * i]; s += v[i]; }
            #pragma unroll
            for (int o = 16; o; o >>= 1) s += __shfl_xor_sync(0xffffffffu, s, o);
            float mu = s * (1.f / HH);
            float q = 0.f;
            #pragma unroll
            for (int i = 0; i < 8; i++) { float d = v[i] - mu; q += d * d; }
            #pragma unroll
            for (int o = 16; o; o >>= 1) q += __shfl_xor_sync(0xffffffffu, q, o);
            float rs = rsqrtf(q * (1.f / HH) + 1e-5f);
            #pragma unroll
            for (int i = 0; i < 8; i++) {
                int cc = lane + 32 * i;
                sB[k * SS + cc] = (v[i] - mu) * rs * lag[cc] + lab[cc];
            }
        }
        __syncthreads();

        // ---- nodeh = gelu(sender@Wn_top + rv) -> sC ----
        {
            ull acc[8][2];
            initacc(acc, sVec, c);
            gemm8x2(acc, sB, SS, HH, W_node + (size_t)e * 2 * HH * HH, HH, c, rbase);
            storeacc(acc, sC, SS, c, rbase, true);
        }
        __syncthreads();

        // ---- msg = gelu(eh@Wm_top + nodeh@Wm_bot + bm) -> sB ----
        {
            const float* Wt = W_msg + (size_t)e * 2 * HH * HH;
            ull acc[8][2];
            initacc(acc, b_msg + e * HH, c);
            gemm8x2(acc, sA, SS, HH, Wt, HH, c, rbase);
            gemm8x2(acc, sC, SS, HH, Wt + (size_t)HH * HH, HH, c, rbase);
            storeacc(acc, sB, SS, c, rbase, true);
        }
        __syncthreads();

        // ---- qkv: q->sA, k->sC, v->sD ----
        {
            const float* W = W_qkv + (size_t)e * HH * 3 * HH;
            const float* bq = b_qkv + e * 3 * HH;
            float* dst0[3] = { sA, sC, sD };
            #pragma unroll 1
            for (int p = 0; p < 3; p++) {
                ull acc[8][2];
                initacc(acc, bq + p * HH, c);
                gemm8x2(acc, sB, SS, HH, W + p * HH, 3 * HH, c, rbase);
                storeacc(acc, dst0[p], SS, c, rbase, false);
            }
        }
        __syncthreads();

        // ---- attention: warp = head (warps 0-7), lane = query. out -> sB ----
        if (wid < 8) {
            int h = wid;
            int a = lane;
            float qv[DHn];
            #pragma unroll
            for (int d = 0; d < DHn; d++) qv[d] = sA[a * SS + h * DHn + d];
            float sc[KK];
            const float scale = 0.17677669529663687f;   // 1/sqrt(32)
            #pragma unroll
            for (int b = 0; b < KK; b++) {
                float s = 0.f;
                #pragma unroll
                for (int d = 0; d < DHn; d++) s = fmaf(qv[d], sC[b * SS + h * DHn + d], s);
                sc[b] = s * scale + sAm[b];
            }
            float m = sc[0];
            #pragma unroll
            for (int b = 1; b < KK; b++) m = fmaxf(m, sc[b]);
            float ssum = 0.f;
            #pragma unroll
            for (int b = 0; b < KK; b++) { sc[b] = expf(sc[b] - m); ssum += sc[b]; }
            float inv = 1.f / ssum;
            float o[DHn];
            #pragma unroll
            for (int d = 0; d < DHn; d++) o[d] = 0.f;
            #pragma unroll
            for (int b = 0; b < KK; b++) {
                float p = sc[b] * inv;
                #pragma unroll
                for (int d = 0; d < DHn; d++) o[d] = fmaf(p, sD[b * SS + h * DHn + d], o[d]);
            }
            #pragma unroll
            for (int d = 0; d < DHn; d++) sB[a * SS + h * DHn + d] = o[d];
        }
        __syncthreads();

        // ---- edge_out = attn_out @ Wo + bo -> sD ----
        {
            ull acc[8][2];
            initacc(acc, b_out + e * HH, c);
            gemm8x2(acc, sB, SS, HH, W_out + (size_t)e * HH * HH, HH, c, rbase);
            storeacc(acc, sD, SS, c, rbase, false);
        }
        __syncthreads();

        // ---- masked-mean aggregate -> nfj ----
        float nfj = 0.f;
        if (tid < HH) {
            float s = 0.f;
            #pragma unroll
            for (int k = 0; k < KK; k++) s += sD[k * SS + j] * sMsk[k];
            nfj = s * inv_cnt + xj;
        }
        __syncthreads();
        // ---- ef = edge_out + edge_features (in place in sD) ----
        for (int idx = tid; idx < KK * HH; idx += 512) {
            int row = idx >> 8, col = idx & 255;
            sD[row * SS + col] += edge_features[(size_t)n * KK * HH + idx];
        }
        __syncthreads();

        // ---- node FFN ----
        float node_final = 0.f;
        {
            float s = block_sum512(nfj, sRed);
            float mu = s * (1.f / HH);
            float d = (tid < HH) ? (nfj - mu) : 0.f;
            float q = block_sum512(d * d, sRed);
            float rs = rsqrtf(q * (1.f / HH) + 1e-5f);
            if (tid < HH) sVec[j] = d * rs * lfg[j] + lfb[j];
        }
        __syncthreads();
        {
            // W1n: 512 outputs, one per thread
            const float* W = W1n + (size_t)e * HH * FF;
            float a0 = b1n[e * FF + tid];
            #pragma unroll 4
            for (int i = 0; i < HH; i++) a0 = fmaf(sVec[i], W[(size_t)i * FF + tid], a0);
            sHn[tid] = gelu_f(a0);
        }
        __syncthreads();
        if (tid < HH) {
            const float* W = W2n + (size_t)e * FF * HH;
            float acc = b2n[e * HH + j];
            #pragma unroll 4
            for (int i = 0; i < FF; i++) acc = fmaf(sHn[i], W[(size_t)i * HH + j], acc);
            node_final = nfj + acc;
        }

        // ---- edge FFN: eh2 = LN(ef) -> sA ----
        for (int k = wid; k < KK; k += 16) {
            float v[8]; float s = 0.f;
            #pragma unroll
            for (int i = 0; i < 8; i++) { v[i] = sD[k * SS + lane + 32 * i]; s += v[i]; }
            #pragma unroll
            for (int o = 16; o; o >>= 1) s += __shfl_xor_sync(0xffffffffu, s, o);
            float mu = s * (1.f / HH);
            float q = 0.f;
            #pragma unroll
            for (int i = 0; i < 8; i++) { float d = v[i] - mu; q += d * d; }
            #pragma unroll
            for (int o = 16; o; o >>= 1) q += __shfl_xor_sync(0xffffffffu, q, o);
            float rs = rsqrtf(q * (1.f / HH) + 1e-5f);
            #pragma unroll
            for (int i = 0; i < 8; i++) {
                int cc = lane + 32 * i;
                sA[k * SS + cc] = (v[i] - mu) * rs * lfg[cc] + lfb[cc];
            }
        }
        __syncthreads();

        // ---- hidden_e = gelu(eh2 @ W1e + b1e) -> sHid [KK x FF] ----
        {
            const float* W = W1e + (size_t)e * HH * FF;
            const float* bb = b1e + e * FF;
            #pragma unroll 1
            for (int p = 0; p < 2; p++) {
                ull acc[8][2];
                initacc(acc, bb + p * 256, c);
                gemm8x2(acc, sA, SS, HH, W + p * 256, FF, c, rbase);
                storeacc(acc, sHid + p * 256, FF, c, rbase, true);
            }
        }
        __syncthreads();

        // ---- ef_final = ef + hidden_e @ W2e + b2e ; write edge output ----
        {
            ull acc[8][2];
            initacc(acc, b2e + e * HH, c);
            gemm8x2(acc, sHid, FF, FF, W2e + (size_t)e * FF * HH, HH, c, rbase);
            float* eout = out + (size_t)NN * HH + (size_t)n * KK * HH;
            if (slot == 0) {
                #pragma unroll
                for (int r = 0; r < 8; r++) {
                    int row = rbase + r;
                    eout[(size_t)row * HH + c]       = gate * (sD[row * SS + c] + fold(acc[r][0]));
                    eout[(size_t)row * HH + c + 128] = gate * (sD[row * SS + c + 128] + fold(acc[r][1]));
                }
            } else {
                #pragma unroll
                for (int r = 0; r < 8; r++) {
                    int row = rbase + r;
                    eout[(size_t)row * HH + c]       += gate * (sD[row * SS + c] + fold(acc[r][0]));
                    eout[(size_t)row * HH + c + 128] += gate * (sD[row * SS + c + 128] + fold(acc[r][1]));
                }
            }
        }
        // ---- node output ----
        if (tid < HH) {
            float* nout = out + (size_t)n * HH;
            if (slot == 0) nout[j] = gate * node_final;
            else           nout[j] += gate * node_final;
        }
        __syncthreads();   // buffers reused by next expert
    }
}

static constexpr int SMEM_FLOATS = 4 * KK * SS + KK * FF + HH + HH + FF + KK + KK + 16;
static constexpr int SMEM_BYTES  = SMEM_FLOATS * 4;

extern "C" void kernel_launch(void* const* d_in, const int* in_sizes, int n_in,
                              void* d_out, int out_size) {
    const float* node_features = (const float*)d_in[0];
    const float* edge_features = (const float*)d_in[1];
    const float* edge_raw      = (const float*)d_in[2];
    const int*   neighbor_list = (const int*)  d_in[3];
    const float* neighbor_mask = (const float*)d_in[4];
    const float* attn_mask     = (const float*)d_in[5];
    const float* w_gate        = (const float*)d_in[6];
    const float* W_edge = (const float*)d_in[7];
    const float* b_edge = (const float*)d_in[8];
    const float* W_node = (const float*)d_in[9];
    const float* b_node = (const float*)d_in[10];
    const float* W_msg  = (const float*)d_in[11];
    const float* b_msg  = (const float*)d_in[12];
    const float* W_qkv  = (const float*)d_in[13];
    const float* b_qkv  = (const float*)d_in[14];
    const float* W_out  = (const float*)d_in[15];
    const float* b_out  = (const float*)d_in[16];
    const float* lag    = (const float*)d_in[17];
    const float* lab    = (const float*)d_in[18];
    const float* lfg    = (const float*)d_in[19];
    const float* lfb    = (const float*)d_in[20];
    const float* W1n = (const float*)d_in[21];
    const float* b1n = (const float*)d_in[22];
    const float* W2n = (const float*)d_in[23];
    const float* b2n = (const float*)d_in[24];
    const float* W1e = (const float*)d_in[25];
    const float* b1e = (const float*)d_in[26];
    const float* W2e = (const float*)d_in[27];
    const float* b2e = (const float*)d_in[28];
    float* out = (float*)d_out;

    cudaFuncSetAttribute(moe_kernel, cudaFuncAttributeMaxDynamicSharedMemorySize, SMEM_BYTES);

    gate_kernel<<<NN, 256>>>(node_features, w_gate);
    moe_kernel<<<NN, 512, SMEM_BYTES>>>(
        node_features, edge_features, edge_raw, neighbor_list, neighbor_mask,
        attn_mask, W_edge, b_edge, W_node, b_node, W_msg, b_msg, W_qkv, b_qkv,
        W_out, b_out, lag, lab, lfg, lfb, W1n, b1n, W2n, b2n, W1e, b1e, W2e, b2e,
        out);
}

// round 3
// speedup vs baseline: 2.1188x; 1.4767x over previous
#include <cuda_runtime.h>
#include <math.h>

#define NN 1024
#define KK 32
#define HH 256
#define DEn 128
#define NE 8
#define NHn 8
#define DHn 32
#define FF 512
#define SS 260   // 16B-aligned padded slot stride

typedef unsigned long long ull;

__device__ int   g_te[NN * 2];
__device__ float g_tg[NN * 2];

// prepacked weights: k-pairs stored as (W[k][j], W[k+1][j]) in one ull
#define OFF_WE   0u
#define OFF_WN   131072u
#define OFF_WM   655360u
#define OFF_WQKV 1179648u
#define OFF_WO   1966080u
#define OFF_W1N  2228224u
#define OFF_W2N  2752512u
#define OFF_W1E  3276800u
#define OFF_W2E  3801088u
#define WP_TOTAL 4325376u
__device__ ull g_wp[WP_TOTAL];

__device__ __forceinline__ float gelu_f(float x) {
    float x3 = x * x * x;
    return 0.5f * x * (1.0f + tanhf(0.7978845608028654f * (x + 0.044715f * x3)));
}
__device__ __forceinline__ ull pk2(float lo, float hi) {
    ull r; asm("mov.b64 %0,{%1,%2};" : "=l"(r) : "f"(lo), "f"(hi)); return r;
}
__device__ __forceinline__ void upk2(ull v, float& lo, float& hi) {
    asm("mov.b64 {%0,%1},%2;" : "=f"(lo), "=f"(hi) : "l"(v));
}
__device__ __forceinline__ void fma2(ull& d, ull a, ull b) {
    asm("fma.rn.f32x2 %0,%1,%2,%0;" : "+l"(d) : "l"(a), "l"(b));
}
__device__ __forceinline__ float fold(ull v) {
    float lo, hi; upk2(v, lo, hi); return lo + hi;
}

__device__ __forceinline__ float block_sum512(float v, float* red) {
    #pragma unroll
    for (int o = 16; o; o >>= 1) v += __shfl_xor_sync(0xffffffffu, v, o);
    int tid = threadIdx.x;
    if ((tid & 31) == 0) red[tid >> 5] = v;
    __syncthreads();
    float s = 0.f;
    #pragma unroll
    for (int i = 0; i < 16; i++) s += red[i];
    __syncthreads();
    return s;
}

// ---- 4-row x 4-col f32x2 GEMM, k-quad inner step ----
__device__ __forceinline__ void initacc4(ull acc[4][4], const float* bias, int cb) {
    #pragma unroll
    for (int jj = 0; jj < 4; jj++) {
        ull b = pk2(bias[cb + 64 * jj], 0.f);
        #pragma unroll
        for (int r = 0; r < 4; r++) acc[r][jj] = b;
    }
}

__device__ __forceinline__ void gemm4x4(ull acc[4][4],
    const float* __restrict__ sIn, int inS, int hin,
    const ull* __restrict__ Wp, int wld, int cb, int rbase)
{
    const float* ip = sIn + rbase * inS;
    #pragma unroll 2
    for (int k = 0; k < hin; k += 4) {
        const ull* wr = Wp + (size_t)(k >> 1) * wld + cb;
        ull wa0 = wr[0], wa1 = wr[64], wa2 = wr[128], wa3 = wr[192];
        const ull* wr2 = wr + wld;
        ull wb0 = wr2[0], wb1 = wr2[64], wb2 = wr2[128], wb3 = wr2[192];
        #pragma unroll
        for (int r = 0; r < 4; r++) {
            ulonglong2 x = *(const ulonglong2*)(ip + r * inS + k);
            fma2(acc[r][0], x.x, wa0); fma2(acc[r][1], x.x, wa1);
            fma2(acc[r][2], x.x, wa2); fma2(acc[r][3], x.x, wa3);
            fma2(acc[r][0], x.y, wb0); fma2(acc[r][1], x.y, wb1);
            fma2(acc[r][2], x.y, wb2); fma2(acc[r][3], x.y, wb3);
        }
    }
}

__device__ __forceinline__ void storeacc4(const ull acc[4][4], float* sOut,
                                          int outS, int cb, int rbase, bool g) {
    #pragma unroll
    for (int r = 0; r < 4; r++)
        #pragma unroll
        for (int jj = 0; jj < 4; jj++) {
            float v = fold(acc[r][jj]);
            if (g) v = gelu_f(v);
            sOut[(rbase + r) * outS + cb + 64 * jj] = v;
        }
}

// ---------------- weight repack: rows k,k+1 -> one ull ----------------
__global__ void repack_kernel(const float* __restrict__ src, ull* __restrict__ dst,
                              int rows2, int cols) {
    int idx = blockIdx.x * blockDim.x + threadIdx.x;
    int total = rows2 * cols;
    int stride = gridDim.x * blockDim.x;
    for (; idx < total; idx += stride) {
        int r2 = idx / cols, cc = idx - r2 * cols;
        dst[idx] = pk2(src[(size_t)(2 * r2) * cols + cc],
                       src[(size_t)(2 * r2 + 1) * cols + cc]);
    }
}

// ---------------- gating kernel ----------------
__global__ void gate_kernel(const float* __restrict__ nf, const float* __restrict__ wg) {
    int n = blockIdx.x;
    int tid = threadIdx.x;
    float x = nf[n * HH + tid];
    float p[NE];
    #pragma unroll
    for (int e = 0; e < NE; e++) p[e] = x * wg[tid * NE + e];
    #pragma unroll
    for (int e = 0; e < NE; e++)
        #pragma unroll
        for (int o = 16; o; o >>= 1) p[e] += __shfl_xor_sync(0xffffffffu, p[e], o);
    __shared__ float logits[NE];
    if (tid < NE) logits[tid] = 0.f;
    __syncthreads();
    if ((tid & 31) == 0) {
        #pragma unroll
        for (int e = 0; e < NE; e++) atomicAdd(&logits[e], p[e]);
    }
    __syncthreads();
    if (tid == 0) {
        float v0 = -1e30f, v1 = -1e30f; int i0 = 0, i1 = 0;
        for (int e = 0; e < NE; e++) {
            float v = logits[e];
            if (v > v0) { v1 = v0; i1 = i0; v0 = v; i0 = e; }
            else if (v > v1) { v1 = v; i1 = e; }
        }
        float e1 = expf(v1 - v0);
        float g0 = 1.f / (1.f + e1);
        g_te[n * 2 + 0] = i0; g_te[n * 2 + 1] = i1;
        g_tg[n * 2 + 0] = g0; g_tg[n * 2 + 1] = 1.f - g0;
    }
}

// ---------------- main kernel: one CTA (512 thr) per node ----------------
__global__ __launch_bounds__(512) void moe_kernel(
    const float* __restrict__ node_features,
    const float* __restrict__ edge_features,
    const float* __restrict__ edge_raw,
    const int*   __restrict__ neighbor_list,
    const float* __restrict__ neighbor_mask,
    const float* __restrict__ attn_mask,
    const float* __restrict__ b_edge, const float* __restrict__ b_node,
    const float* __restrict__ b_msg,  const float* __restrict__ b_qkv,
    const float* __restrict__ b_out,
    const float* __restrict__ lag_, const float* __restrict__ lab_,
    const float* __restrict__ lfg_, const float* __restrict__ lfb_,
    const float* __restrict__ b1n, const float* __restrict__ b2n,
    const float* __restrict__ b1e, const float* __restrict__ b2e,
    float* __restrict__ out)
{
    extern __shared__ float sm[];
    float* sA   = sm;                 // KK*SS
    float* sB   = sA + KK * SS;
    float* sC   = sB + KK * SS;
    float* sD   = sC + KK * SS;
    float* sHid = sD + KK * SS;       // KK*FF (also edge_features staging)
    float* sNh  = sHid + KK * FF;     // HH
    float* sVec = sNh + HH;           // HH
    float* sHn  = sVec + HH;          // FF
    float* sMsk = sHn + FF;           // KK
    float* sAm  = sMsk + KK;          // KK
    float* sRed = sAm + KK;           // 16

    const int n = blockIdx.x;
    const int tid = threadIdx.x;
    const int lane = tid & 31, wid = tid >> 5;
    const int j = tid;                 // element index for <256 stages
    const int cb = tid & 63;           // gemm column base
    const int rbase = (tid >> 6) * 4;  // gemm rows

    if (tid < KK) {
        sMsk[tid] = neighbor_mask[n * KK + tid];
        sAm[tid]  = attn_mask[n * KK + tid];
    }
    __syncthreads();
    float cnt = 0.f;
    #pragma unroll
    for (int k = 0; k < KK; k++) cnt += sMsk[k];
    float inv_cnt = 1.f / (cnt + 1e-5f);

    const float xj = (tid < HH) ? node_features[(size_t)n * HH + j] : 0.f;

    #pragma unroll 1
    for (int slot = 0; slot < 2; slot++) {
        int e = g_te[n * 2 + slot];
        float gate = g_tg[n * 2 + slot];
        const float* lag = lag_ + e * HH;
        const float* lab = lab_ + e * HH;
        const float* lfg = lfg_ + e * HH;
        const float* lfb = lfb_ + e * HH;

        // ---- recv layernorm -> sNh ----
        {
            float s = block_sum512(xj, sRed);
            float mu = s * (1.f / HH);
            float d = (tid < HH) ? (xj - mu) : 0.f;
            float q = block_sum512(d * d, sRed);
            float rs = rsqrtf(q * (1.f / HH) + 1e-5f);
            if (tid < HH) sNh[j] = d * rs * lag[j] + lab[j];
        }
        __syncthreads();

        // ---- rv = recv @ Wn_bottom + bn (warps 0-7) | edge_raw -> sB (warps 8-15) ----
        if (tid < HH) {
            const ull* W = g_wp + OFF_WN + (size_t)e * 65536u + 128u * 256u;
            ull a0 = pk2(b_node[e * HH + j], 0.f);
            ull a1 = pk2(0.f, 0.f);
            #pragma unroll 4
            for (int i = 0; i < 128; i += 2) {
                fma2(a0, *(const ull*)(sNh + 2 * i),     W[(size_t)i * 256 + j]);
                fma2(a1, *(const ull*)(sNh + 2 * i + 2), W[(size_t)(i + 1) * 256 + j]);
            }
            sVec[j] = fold(a0) + fold(a1);
        } else {
            int t2 = tid - 256;
            const float4* src = (const float4*)(edge_raw + (size_t)n * KK * DEn);
            float4* dst = (float4*)sB;
            #pragma unroll
            for (int i = 0; i < 4; i++) dst[t2 + 256 * i] = src[t2 + 256 * i];
        }
        __syncthreads();

        // ---- eh = gelu(edge_raw @ We + be) -> sA ----
        {
            ull acc[4][4];
            initacc4(acc, b_edge + e * HH, cb);
            gemm4x4(acc, sB, DEn, DEn, g_wp + OFF_WE + (size_t)e * 16384u, 256, cb, rbase);
            storeacc4(acc, sA, SS, cb, rbase, true);
        }
        __syncthreads();

        // ---- sender = LN(node_features[nbr]) -> sB (warp per row, 16 warps) ----
        for (int k = wid; k < KK; k += 16) {
            int nbr = neighbor_list[n * KK + k];
            const float* x = node_features + (size_t)nbr * HH;
            float v[8]; float s = 0.f;
            #pragma unroll
            for (int i = 0; i < 8; i++) { v[i] = x[lane + 32 * i]; s += v[i]; }
            #pragma unroll
            for (int o = 16; o; o >>= 1) s += __shfl_xor_sync(0xffffffffu, s, o);
            float mu = s * (1.f / HH);
            float q = 0.f;
            #pragma unroll
            for (int i = 0; i < 8; i++) { float d = v[i] - mu; q += d * d; }
            #pragma unroll
            for (int o = 16; o; o >>= 1) q += __shfl_xor_sync(0xffffffffu, q, o);
            float rs = rsqrtf(q * (1.f / HH) + 1e-5f);
            #pragma unroll
            for (int i = 0; i < 8; i++) {
                int cc = lane + 32 * i;
                sB[k * SS + cc] = (v[i] - mu) * rs * lag[cc] + lab[cc];
            }
        }
        __syncthreads();

        // ---- nodeh = gelu(sender@Wn_top + rv) -> sC ----
        {
            ull acc[4][4];
            initacc4(acc, sVec, cb);
            gemm4x4(acc, sB, SS, HH, g_wp + OFF_WN + (size_t)e * 65536u, 256, cb, rbase);
            storeacc4(acc, sC, SS, cb, rbase, true);
        }
        __syncthreads();

        // ---- msg = gelu(eh@Wm_top + nodeh@Wm_bot + bm) -> sB ----
        {
            const ull* Wt = g_wp + OFF_WM + (size_t)e * 65536u;
            ull acc[4][4];
            initacc4(acc, b_msg + e * HH, cb);
            gemm4x4(acc, sA, SS, HH, Wt, 256, cb, rbase);
            gemm4x4(acc, sC, SS, HH, Wt + 128u * 256u, 256, cb, rbase);
            storeacc4(acc, sB, SS, cb, rbase, true);
        }
        __syncthreads();

        // ---- qkv: q->sA, k->sC, v->sD ----
        {
            const ull* W = g_wp + OFF_WQKV + (size_t)e * 98304u;
            const float* bq = b_qkv + e * 3 * HH;
            float* dst0[3] = { sA, sC, sD };
            #pragma unroll 1
            for (int p = 0; p < 3; p++) {
                ull acc[4][4];
                initacc4(acc, bq, p * 256 + cb);
                gemm4x4(acc, sB, SS, HH, W, 768, p * 256 + cb, rbase);
                storeacc4(acc, dst0[p], SS, cb, rbase, false);
            }
        }
        __syncthreads();

        // ---- attention (warps 0-7) | edge_features -> sHid (warps 8-15) ----
        if (wid < 8) {
            int h = wid;
            int a = lane;
            float qv[DHn];
            #pragma unroll
            for (int d = 0; d < DHn; d++) qv[d] = sA[a * SS + h * DHn + d];
            float sc[KK];
            const float scale = 0.17677669529663687f;   // 1/sqrt(32)
            #pragma unroll
            for (int b = 0; b < KK; b++) {
                float s = 0.f;
                #pragma unroll
                for (int d = 0; d < DHn; d++) s = fmaf(qv[d], sC[b * SS + h * DHn + d], s);
                sc[b] = s * scale + sAm[b];
            }
            float m = sc[0];
            #pragma unroll
            for (int b = 1; b < KK; b++) m = fmaxf(m, sc[b]);
            float ssum = 0.f;
            #pragma unroll
            for (int b = 0; b < KK; b++) { sc[b] = expf(sc[b] - m); ssum += sc[b]; }
            float inv = 1.f / ssum;
            float o[DHn];
            #pragma unroll
            for (int d = 0; d < DHn; d++) o[d] = 0.f;
            #pragma unroll
            for (int b = 0; b < KK; b++) {
                float p = sc[b] * inv;
                #pragma unroll
                for (int d = 0; d < DHn; d++) o[d] = fmaf(p, sD[b * SS + h * DHn + d], o[d]);
            }
            #pragma unroll
            for (int d = 0; d < DHn; d++) sB[a * SS + h * DHn + d] = o[d];
        } else {
            int t2 = tid - 256;
            const float4* src = (const float4*)(edge_features + (size_t)n * KK * HH);
            float4* dst = (float4*)sHid;
            #pragma unroll
            for (int i = 0; i < 8; i++) dst[t2 + 256 * i] = src[t2 + 256 * i];
        }
        __syncthreads();

        // ---- edge_out = attn_out @ Wo + bo -> sD ----
        {
            ull acc[4][4];
            initacc4(acc, b_out + e * HH, cb);
            gemm4x4(acc, sB, SS, HH, g_wp + OFF_WO + (size_t)e * 32768u, 256, cb, rbase);
            storeacc4(acc, sD, SS, cb, rbase, false);
        }
        __syncthreads();

        // ---- masked-mean aggregate -> nfj (pre ef-add) ----
        float nfj = 0.f;
        if (tid < HH) {
            float s = 0.f;
            #pragma unroll
            for (int k = 0; k < KK; k++) s += sD[k * SS + j] * sMsk[k];
            nfj = s * inv_cnt + xj;
        }
        __syncthreads();
        // ---- ef = edge_out + edge_features (staged in sHid) ----
        for (int idx = tid; idx < KK * HH; idx += 512) {
            int row = idx >> 8, col = idx & 255;
            sD[row * SS + col] += sHid[idx];
        }
        __syncthreads();

        // ---- node FFN LN -> sVec ----
        {
            float s = block_sum512(nfj, sRed);
            float mu = s * (1.f / HH);
            float d = (tid < HH) ? (nfj - mu) : 0.f;
            float q = block_sum512(d * d, sRed);
            float rs = rsqrtf(q * (1.f / HH) + 1e-5f);
            if (tid < HH) sVec[j] = d * rs * lfg[j] + lfb[j];
        }
        __syncthreads();
        // ---- W1n: 512 outputs, one per thread ----
        {
            const ull* W = g_wp + OFF_W1N + (size_t)e * 65536u;
            ull a0 = pk2(b1n[e * FF + tid], 0.f);
            ull a1 = pk2(0.f, 0.f);
            #pragma unroll 4
            for (int i = 0; i < 128; i += 2) {
                fma2(a0, *(const ull*)(sVec + 2 * i),     W[(size_t)i * 512 + tid]);
                fma2(a1, *(const ull*)(sVec + 2 * i + 2), W[(size_t)(i + 1) * 512 + tid]);
            }
            sHn[tid] = gelu_f(fold(a0) + fold(a1));
        }
        __syncthreads();

        // ---- W2n (warps 0-7) | edge LN: sD -> sA (warps 8-15) ----
        float node_final = 0.f;
        if (tid < HH) {
            const ull* W = g_wp + OFF_W2N + (size_t)e * 65536u;
            ull a0 = pk2(b2n[e * HH + j], 0.f);
            ull a1 = pk2(0.f, 0.f);
            #pragma unroll 4
            for (int i = 0; i < 256; i += 2) {
                fma2(a0, *(const ull*)(sHn + 2 * i),     W[(size_t)i * 256 + j]);
                fma2(a1, *(const ull*)(sHn + 2 * i + 2), W[(size_t)(i + 1) * 256 + j]);
            }
            node_final = nfj + fold(a0) + fold(a1);
        } else {
            for (int k = wid - 8; k < KK; k += 8) {
                float v[8]; float s = 0.f;
                #pragma unroll
                for (int i = 0; i < 8; i++) { v[i] = sD[k * SS + lane + 32 * i]; s += v[i]; }
                #pragma unroll
                for (int o = 16; o; o >>= 1) s += __shfl_xor_sync(0xffffffffu, s, o);
                float mu = s * (1.f / HH);
                float q = 0.f;
                #pragma unroll
                for (int i = 0; i < 8; i++) { float d = v[i] - mu; q += d * d; }
                #pragma unroll
                for (int o = 16; o; o >>= 1) q += __shfl_xor_sync(0xffffffffu, q, o);
                float rs = rsqrtf(q * (1.f / HH) + 1e-5f);
                #pragma unroll
                for (int i = 0; i < 8; i++) {
                    int cc = lane + 32 * i;
                    sA[k * SS + cc] = (v[i] - mu) * rs * lfg[cc] + lfb[cc];
                }
            }
        }
        __syncthreads();

        // ---- hidden_e = gelu(eh2 @ W1e + b1e) -> sHid [KK x FF] ----
        {
            const ull* W = g_wp + OFF_W1E + (size_t)e * 65536u;
            const float* bb = b1e + e * FF;
            #pragma unroll 1
            for (int p = 0; p < 2; p++) {
                ull acc[4][4];
                initacc4(acc, bb, p * 256 + cb);
                gemm4x4(acc, sA, SS, HH, W, 512, p * 256 + cb, rbase);
                storeacc4(acc, sHid, FF, p * 256 + cb, rbase, true);
            }
        }
        __syncthreads();

        // ---- ef_final = ef + hidden_e @ W2e + b2e ; write outputs ----
        {
            ull acc[4][4];
            initacc4(acc, b2e + e * HH, cb);
            gemm4x4(acc, sHid, FF, FF, g_wp + OFF_W2E + (size_t)e * 65536u, 256, cb, rbase);
            float* eout = out + (size_t)NN * HH + (size_t)n * KK * HH;
            if (slot == 0) {
                #pragma unroll
                for (int r = 0; r < 4; r++)
                    #pragma unroll
                    for (int jj = 0; jj < 4; jj++) {
                        int row = rbase + r, col = cb + 64 * jj;
                        eout[(size_t)row * HH + col] =
                            gate * (sD[row * SS + col] + fold(acc[r][jj]));
                    }
            } else {
                #pragma unroll
                for (int r = 0; r < 4; r++)
                    #pragma unroll
                    for (int jj = 0; jj < 4; jj++) {
                        int row = rbase + r, col = cb + 64 * jj;
                        eout[(size_t)row * HH + col] +=
                            gate * (sD[row * SS + col] + fold(acc[r][jj]));
                    }
            }
        }
        if (tid < HH) {
            float* nout = out + (size_t)n * HH;
            if (slot == 0) nout[j] = gate * node_final;
            else           nout[j] += gate * node_final;
        }
        __syncthreads();   // buffers reused by next expert
    }
}

static constexpr int SMEM_FLOATS = 4 * KK * SS + KK * FF + HH + HH + FF + KK + KK + 16;
static constexpr int SMEM_BYTES  = SMEM_FLOATS * 4;

extern "C" void kernel_launch(void* const* d_in, const int* in_sizes, int n_in,
                              void* d_out, int out_size) {
    const float* node_features = (const float*)d_in[0];
    const float* edge_features = (const float*)d_in[1];
    const float* edge_raw      = (const float*)d_in[2];
    const int*   neighbor_list = (const int*)  d_in[3];
    const float* neighbor_mask = (const float*)d_in[4];
    const float* attn_mask     = (const float*)d_in[5];
    const float* w_gate        = (const float*)d_in[6];
    const float* W_edge = (const float*)d_in[7];
    const float* b_edge = (const float*)d_in[8];
    const float* W_node = (const float*)d_in[9];
    const float* b_node = (const float*)d_in[10];
    const float* W_msg  = (const float*)d_in[11];
    const float* b_msg  = (const float*)d_in[12];
    const float* W_qkv  = (const float*)d_in[13];
    const float* b_qkv  = (const float*)d_in[14];
    const float* W_out  = (const float*)d_in[15];
    const float* b_out  = (const float*)d_in[16];
    const float* lag    = (const float*)d_in[17];
    const float* lab    = (const float*)d_in[18];
    const float* lfg    = (const float*)d_in[19];
    const float* lfb    = (const float*)d_in[20];
    const float* W1n = (const float*)d_in[21];
    const float* b1n = (const float*)d_in[22];
    const float* W2n = (const float*)d_in[23];
    const float* b2n = (const float*)d_in[24];
    const float* W1e = (const float*)d_in[25];
    const float* b1e = (const float*)d_in[26];
    const float* W2e = (const float*)d_in[27];
    const float* b2e = (const float*)d_in[28];
    float* out = (float*)d_out;

    ull* wp = nullptr;
    cudaGetSymbolAddress((void**)&wp, g_wp);

    cudaFuncSetAttribute(moe_kernel, cudaFuncAttributeMaxDynamicSharedMemorySize, SMEM_BYTES);

    // repack weights into k-pair float2 layout
    repack_kernel<<<256, 256>>>(W_edge, wp + OFF_WE,   512, 256);
    repack_kernel<<<256, 256>>>(W_node, wp + OFF_WN,  2048, 256);
    repack_kernel<<<256, 256>>>(W_msg,  wp + OFF_WM,  2048, 256);
    repack_kernel<<<256, 256>>>(W_qkv,  wp + OFF_WQKV,1024, 768);
    repack_kernel<<<256, 256>>>(W_out,  wp + OFF_WO,  1024, 256);
    repack_kernel<<<256, 256>>>(W1n,    wp + OFF_W1N, 1024, 512);
    repack_kernel<<<256, 256>>>(W2n,    wp + OFF_W2N, 2048, 256);
    repack_kernel<<<256, 256>>>(W1e,    wp + OFF_W1E, 1024, 512);
    repack_kernel<<<256, 256>>>(W2e,    wp + OFF_W2E, 2048, 256);

    gate_kernel<<<NN, 256>>>(node_features, w_gate);

    moe_kernel<<<NN, 512, SMEM_BYTES>>>(
        node_features, edge_features, edge_raw, neighbor_list, neighbor_mask,
        attn_mask, b_edge, b_node, b_msg, b_qkv, b_out,
        lag, lab, lfg, lfb, b1n, b2n, b1e, b2e, out);
}